// round 6
// baseline (speedup 1.0000x reference)
#include <cuda_runtime.h>
#include <cstdint>

#define N_IMG 8192

// ---------------- scratch (device globals; no allocations) ----------------
__device__ float    g_Ppart[128 * 1024];     // partial batch sums of x
__device__ float    g_thr[20];               // per-channel BN mean (threshold)
__device__ unsigned g_b1[N_IMG * 196];       // binarized pool1: 20 channel bits per (n,py,px)
__device__ unsigned g_wp2[50 * 25];          // conv2 sign(W)>0 masks (20 bits over c)
__device__ unsigned g_wz2[50 * 25];          // conv2 W==0 masks
__device__ int      g_zflag2;                // any zero conv2 weight
__device__ unsigned g_wpl[500 * 40];         // linear sign(W)>0 masks (1250 bits)
__device__ unsigned g_wzl[500 * 40];         // linear W==0 masks
__device__ int      g_zflagl;
__device__ float    g_alphal[500];           // linear alpha = mean(|W|, dim=1)
__device__ unsigned g_Bp[N_IMG * 40];        // sign(+1) bit-plane into linear
__device__ unsigned g_Bn[N_IMG * 40];        // sign(-1) bit-plane into linear

// ---------------- K_pre: fused colsum + weight masks + alpha_l ------------
__global__ __launch_bounds__(256) void k_pre(const float* __restrict__ x,
                                             const float* __restrict__ w2,
                                             const float* __restrict__ wl) {
    int b = blockIdx.x, t = threadIdx.x;
    if (b < 128) {
        const float* base = x + (size_t)b * 64 * 1024 + t * 4;
        float4 acc = make_float4(0.f, 0.f, 0.f, 0.f);
        for (int i = 0; i < 64; ++i) {
            float4 v = *(const float4*)(base + (size_t)i * 1024);
            acc.x += v.x; acc.y += v.y; acc.z += v.z; acc.w += v.w;
        }
        *(float4*)(g_Ppart + b * 1024 + t * 4) = acc;
    } else if (b < 144) {
        int gid = (b - 128) * 256 + t;           // 0..4095
        if (gid < 1250) {                         // conv2 masks
            int oc = gid / 25, d = gid % 25;
            unsigned mp = 0, mz = 0;
            for (int c = 0; c < 20; ++c) {
                float w = w2[oc * 500 + c * 25 + d];
                if (w > 0.f) mp |= 1u << c;
                else if (w == 0.f) mz |= 1u << c;
            }
            g_wp2[gid] = mp; g_wz2[gid] = mz;
            if (mz) atomicOr(&g_zflag2, 1);
        }
        for (int e = gid; e < 500 * 40; e += 4096) {  // linear masks
            int j = e / 40, wi = e % 40;
            unsigned mp = 0, mz = 0;
            for (int bit = 0; bit < 32; ++bit) {
                int i = wi * 32 + bit;
                if (i < 1250) {
                    float w = wl[j * 1250 + i];
                    if (w > 0.f) mp |= 1u << bit;
                    else if (w == 0.f) mz |= 1u << bit;
                }
            }
            g_wpl[e] = mp; g_wzl[e] = mz;
            if (mz) atomicOr(&g_zflagl, 1);
        }
    } else {
        int w = (b - 144) * 8 + (t >> 5);        // row index
        int lane = t & 31;
        if (w < 500) {
            double s = 0.0;
            for (int i = lane; i < 1250; i += 32)
                s += fabs((double)wl[w * 1250 + i]);
#pragma unroll
            for (int o = 16; o; o >>= 1) s += __shfl_down_sync(0xffffffffu, s, o);
            if (lane == 0) g_alphal[w] = (float)(s / 1250.0);
        }
    }
}

// ---------------- K1b: reduce partials -> P, T[5][5], thresholds ----------
__global__ __launch_bounds__(1024) void k_thr(const float* __restrict__ w1) {
    __shared__ double Ps[1024];
    __shared__ double Ts[25];
    int t = threadIdx.x;
    double s0 = 0.0, s1 = 0.0;
    for (int i = 0; i < 128; i += 2) {
        s0 += (double)g_Ppart[i * 1024 + t];
        s1 += (double)g_Ppart[(i + 1) * 1024 + t];
    }
    Ps[t] = s0 + s1;
    __syncthreads();
    if (t < 800) {                    // 25 taps x 32 lanes, fixed shfl tree
        int g = t >> 5, lane = t & 31;
        int dy = g / 5, dx = g % 5;
        double a = 0.0;
        for (int idx = lane; idx < 784; idx += 32) {
            int i = idx / 28, j = idx % 28;
            a += Ps[(i + dy) * 32 + (j + dx)];
        }
#pragma unroll
        for (int o = 16; o; o >>= 1) a += __shfl_down_sync(0xffffffffu, a, o);
        if (lane == 0) Ts[g] = a;
    }
    __syncthreads();
    if (t < 20) {
        double d = 0.0;
        for (int k = 0; k < 25; ++k) d += (double)w1[t * 25 + k] * Ts[k];
        g_thr[t] = (float)(d / (8192.0 * 28.0 * 28.0));
    }
}

// ---------------- K2: conv1 + threshold + 2x2 pool + channel bit-pack -----
__global__ __launch_bounds__(224) void k_conv1(const float* __restrict__ x,
                                               const float* __restrict__ w1) {
    __shared__ float xs[1024];
    __shared__ float ws[20 * 28];
    __shared__ float thr_s[20];
    int n = blockIdx.x, t = threadIdx.x;
    for (int i = t; i < 1024; i += 224) xs[i] = x[(size_t)n * 1024 + i];
    for (int i = t; i < 500; i += 224) ws[(i / 25) * 28 + (i % 25)] = w1[i];
    if (t < 20) thr_s[t] = g_thr[t];
    __syncthreads();
    if (t < 196) {
        int py = t / 14, px = t % 14;
        float xp[6][6];
        const float* xb = &xs[(py * 2) * 32 + px * 2];
#pragma unroll
        for (int r = 0; r < 6; ++r) {
#pragma unroll
            for (int c2 = 0; c2 < 3; ++c2) {
                float2 v = *(const float2*)(xb + r * 32 + c2 * 2);
                xp[r][c2 * 2] = v.x; xp[r][c2 * 2 + 1] = v.y;
            }
        }
        unsigned word = 0;
#pragma unroll 1
        for (int c = 0; c < 20; ++c) {
            const float* wc = &ws[c * 28];
            float a0 = 0.f, a1 = 0.f, a2 = 0.f, a3 = 0.f;
#pragma unroll
            for (int dy = 0; dy < 5; ++dy) {
#pragma unroll
                for (int dx = 0; dx < 5; ++dx) {
                    float w = wc[dy * 5 + dx];
                    a0 = fmaf(w, xp[dy][dx],         a0);
                    a1 = fmaf(w, xp[dy][dx + 1],     a1);
                    a2 = fmaf(w, xp[dy + 1][dx],     a2);
                    a3 = fmaf(w, xp[dy + 1][dx + 1], a3);
                }
            }
            float m = fmaxf(fmaxf(a0, a1), fmaxf(a2, a3));
            if (m > thr_s[c]) word |= (1u << c);
        }
        g_b1[n * 196 + t] = word;
    }
}

// ---------------- K3: XNOR conv2, reg-weights + uint2 b-loads -------------
#define C2_IMGS 4
__global__ __launch_bounds__(320, 4) void k_conv2() {
    __shared__ __align__(8) unsigned Bs[C2_IMGS][196];
    __shared__ int pc[C2_IMGS][196];
    __shared__ int PB[C2_IMGS][100];
    __shared__ unsigned Wps[50 * 25];
    __shared__ unsigned Wzs[50 * 25];
    int n0 = blockIdx.x * C2_IMGS, t = threadIdx.x;
    for (int i = t; i < C2_IMGS * 196; i += 320) {
        int img = i / 196, p = i % 196;
        unsigned bv = g_b1[(size_t)(n0 + img) * 196 + p];
        Bs[img][p] = bv; pc[img][p] = __popc(bv);
    }
    int zf = g_zflag2;
    for (int i = t; i < 1250; i += 320) Wps[i] = g_wp2[i];
    if (zf) for (int i = t; i < 1250; i += 320) Wzs[i] = g_wz2[i];
    __syncthreads();
    for (int i = t; i < C2_IMGS * 100; i += 320) {
        int img = i / 100, p = i % 100;
        int y = p / 10, xx = p % 10;
        int s = 0;
#pragma unroll
        for (int dy = 0; dy < 5; ++dy)
#pragma unroll
            for (int dx = 0; dx < 5; ++dx) s += pc[img][(y + dy) * 14 + xx + dx];
        PB[img][p] = s;
    }
    __syncthreads();
    int lane = t & 31, w = t >> 5;
#pragma unroll 1
    for (int k = 0; k < 4; ++k) {
        int f = k * 320 + t;
        int valid = f < 1250;
        int fc = valid ? f : 0;
        int oc = fc / 25; int rem = fc - oc * 25; int r = rem / 5; int cx = rem - r * 5;
        unsigned W[25];
#pragma unroll
        for (int i = 0; i < 25; ++i) W[i] = Wps[oc * 25 + i];
#pragma unroll 1
        for (int img = 0; img < C2_IMGS; ++img) {
            const unsigned* brow = &Bs[img][(2 * r) * 14 + 2 * cx];
            int a00 = 0, a01 = 0, a10 = 0, a11 = 0;
#pragma unroll
            for (int rr = 0; rr < 6; ++rr) {
                uint2 p0 = *(const uint2*)(brow + rr * 14);
                uint2 p1 = *(const uint2*)(brow + rr * 14 + 2);
                uint2 p2 = *(const uint2*)(brow + rr * 14 + 4);
                unsigned b0 = p0.x, b1 = p0.y, b2 = p1.x,
                         b3 = p1.y, b4 = p2.x, b5 = p2.y;
                if (rr < 5) {                 // pool row oy=0, W row rr
                    unsigned w0 = W[rr * 5], w1 = W[rr * 5 + 1], w2 = W[rr * 5 + 2],
                             w3 = W[rr * 5 + 3], w4 = W[rr * 5 + 4];
                    a00 += __popc(b0 & w0) + __popc(b1 & w1) + __popc(b2 & w2)
                         + __popc(b3 & w3) + __popc(b4 & w4);
                    a01 += __popc(b1 & w0) + __popc(b2 & w1) + __popc(b3 & w2)
                         + __popc(b4 & w3) + __popc(b5 & w4);
                }
                if (rr >= 1) {                // pool row oy=1, W row rr-1
                    unsigned w0 = W[(rr - 1) * 5], w1 = W[(rr - 1) * 5 + 1],
                             w2 = W[(rr - 1) * 5 + 2], w3 = W[(rr - 1) * 5 + 3],
                             w4 = W[(rr - 1) * 5 + 4];
                    a10 += __popc(b0 & w0) + __popc(b1 & w1) + __popc(b2 & w2)
                         + __popc(b3 & w3) + __popc(b4 & w4);
                    a11 += __popc(b1 & w0) + __popc(b2 & w1) + __popc(b3 & w2)
                         + __popc(b4 & w3) + __popc(b5 & w4);
                }
            }
            int bitP = 0, bitN = 0;
            if (valid) {
                int v00 = 2 * a00 - PB[img][(2 * r) * 10 + 2 * cx];
                int v01 = 2 * a01 - PB[img][(2 * r) * 10 + 2 * cx + 1];
                int v10 = 2 * a10 - PB[img][(2 * r + 1) * 10 + 2 * cx];
                int v11 = 2 * a11 - PB[img][(2 * r + 1) * 10 + 2 * cx + 1];
                if (zf) {  // uniform, never taken with this dataset
                    const unsigned* Wz = &Wzs[oc * 25];
                    int z00 = 0, z01 = 0, z10 = 0, z11 = 0;
                    for (int dy = 0; dy < 5; ++dy)
                        for (int dx = 0; dx < 5; ++dx) {
                            unsigned wz = Wz[dy * 5 + dx];
                            z00 += __popc(brow[dy * 14 + dx] & wz);
                            z01 += __popc(brow[dy * 14 + dx + 1] & wz);
                            z10 += __popc(brow[(dy + 1) * 14 + dx] & wz);
                            z11 += __popc(brow[(dy + 1) * 14 + dx + 1] & wz);
                        }
                    v00 += z00; v01 += z01; v10 += z10; v11 += z11;
                }
                int best = max(max(v00, v01), max(v10, v11));
                bitP = best > 0; bitN = best < 0;
            }
            unsigned mp = __ballot_sync(0xffffffffu, bitP);
            unsigned mn = __ballot_sync(0xffffffffu, bitN);
            if (lane == 0) {
                int wi = k * 10 + w;
                g_Bp[(size_t)(n0 + img) * 40 + wi] = mp;
                g_Bn[(size_t)(n0 + img) * 40 + wi] = mn;
            }
        }
    }
}

// ---------------- K4: binary linear (XNOR-LOP3) + clip + fc ---------------
__global__ __launch_bounds__(256) void k_dense(const float* __restrict__ fcw,
                                               const float* __restrict__ fcb,
                                               float* __restrict__ out) {
    extern __shared__ unsigned sm[];
    unsigned* Ws  = sm;                       // 500*41 (padded, conflict-free)
    unsigned* Bps = Ws + 500 * 41;            // 8*40  sign bit-plane (+1)
    unsigned* Bns = Bps + 8 * 40;             // 8*40  sign bit-plane (-1), zf path only
    unsigned* Us  = Bns + 8 * 40;             // 8*40  nonzero mask = Bp|Bn
    int*      pcU = (int*)(Us + 8 * 40);      // 8
    float*    hs  = (float*)(pcU + 8);        // 8*500
    int t = threadIdx.x;
    int n0 = blockIdx.x * 8;
    for (int i = t; i < 500 * 40; i += 256) Ws[(i / 40) * 41 + (i % 40)] = g_wpl[i];
    for (int i = t; i < 320; i += 256) {
        int img = i / 40, wi = i % 40;
        unsigned bp = g_Bp[(size_t)(n0 + img) * 40 + wi];
        unsigned bn = g_Bn[(size_t)(n0 + img) * 40 + wi];
        Bps[img * 40 + wi] = bp;
        Bns[img * 40 + wi] = bn;
        Us[img * 40 + wi]  = bp | bn;
    }
    __syncthreads();
    if (t < 8) {
        int s = 0;
        for (int k = 0; k < 40; ++k) s += __popc(Us[t * 40 + k]);
        pcU[t] = s;
    }
    __syncthreads();
    int zf = g_zflagl;
    for (int j = t; j < 500; j += 256) {
        unsigned wr[40];
#pragma unroll
        for (int k = 0; k < 40; ++k) wr[k] = Ws[j * 41 + k];
        float al = g_alphal[j];
#pragma unroll 1
        for (int img = 0; img < 8; ++img) {
            int m = 0;
#pragma unroll
            for (int k = 0; k < 40; ++k) {
                // agreement over nonzero lanes: one LOP3 per word
                m += __popc((~(Bps[img * 40 + k] ^ wr[k])) & Us[img * 40 + k]);
            }
            int vi = 2 * m - pcU[img];
            if (zf) {  // uniform, never taken with this dataset
                int cp = 0, cn = 0;
                for (int k = 0; k < 40; ++k) {
                    unsigned z = g_wzl[j * 40 + k];
                    cp += __popc(Bps[img * 40 + k] & z);
                    cn += __popc(Bns[img * 40 + k] & z);
                }
                vi += cp - cn;
            }
            float h = fminf(fmaxf((float)vi * al, -1.f), 1.f);
            hs[img * 500 + j] = h;
        }
    }
    __syncthreads();
    int w = t >> 5, lane = t & 31;   // warp w -> image w
    for (int lg = 0; lg < 10; ++lg) {
        float p = 0.f;
        for (int j = lane; j < 500; j += 32)
            p += hs[w * 500 + j] * __ldg(&fcw[lg * 500 + j]);
#pragma unroll
        for (int o = 16; o; o >>= 1) p += __shfl_down_sync(0xffffffffu, p, o);
        if (lane == 0) out[(size_t)(n0 + w) * 10 + lg] = p + fcb[lg];
    }
}

// ---------------- launch ---------------------------------------------------
extern "C" void kernel_launch(void* const* d_in, const int* in_sizes, int n_in,
                              void* d_out, int out_size) {
    const float* x   = (const float*)d_in[0];
    const float* w1  = (const float*)d_in[1];
    const float* w2  = (const float*)d_in[2];
    const float* wl  = (const float*)d_in[3];
    const float* fcw = (const float*)d_in[4];
    const float* fcb = (const float*)d_in[5];
    float* out = (float*)d_out;

    size_t dense_smem = (500 * 41 + 8 * 40 * 3 + 8) * 4 + 8 * 500 * 4;
    cudaFuncSetAttribute(k_dense, cudaFuncAttributeMaxDynamicSharedMemorySize,
                         (int)dense_smem);

    k_pre<<<207, 256>>>(x, w2, wl);
    k_thr<<<1, 1024>>>(w1);
    k_conv1<<<8192, 224>>>(x, w1);
    k_conv2<<<N_IMG / C2_IMGS, 320>>>();
    k_dense<<<1024, 256, dense_smem>>>(fcw, fcb, out);
}

// round 7
// speedup vs baseline: 1.0245x; 1.0245x over previous
#include <cuda_runtime.h>
#include <cstdint>

#define N_IMG 8192

// ---------------- scratch (device globals; no allocations) ----------------
__device__ float    g_Ppart[128 * 1024];     // partial batch sums of x
__device__ float    g_thr[20];               // per-channel BN mean (threshold)
__device__ unsigned g_b1[N_IMG * 196];       // binarized pool1: 20 channel bits per (n,py,px)
__device__ unsigned g_wp2[50 * 25];          // conv2 sign(W)>0 masks (20 bits over c)
__device__ unsigned g_wp2p[50 * 5 * 8];      // conv2 masks, 8-word padded rows (w0..w4,0,0,0)
__device__ unsigned g_wz2[50 * 25];          // conv2 W==0 masks
__device__ int      g_zflag2;                // any zero conv2 weight
__device__ unsigned g_wpl[500 * 40];         // linear sign(W)>0 masks (1250 bits)
__device__ unsigned g_wzl[500 * 40];         // linear W==0 masks
__device__ int      g_zflagl;
__device__ float    g_alphal[500];           // linear alpha = mean(|W|, dim=1)
__device__ unsigned g_Bp[N_IMG * 40];        // sign(+1) bit-plane into linear
__device__ unsigned g_Bn[N_IMG * 40];        // sign(-1) bit-plane into linear

// ---------------- K_pre: fused colsum + weight masks + alpha_l ------------
__global__ __launch_bounds__(256) void k_pre(const float* __restrict__ x,
                                             const float* __restrict__ w2,
                                             const float* __restrict__ wl) {
    int b = blockIdx.x, t = threadIdx.x;
    if (b < 128) {
        const float* base = x + (size_t)b * 64 * 1024 + t * 4;
        float4 acc = make_float4(0.f, 0.f, 0.f, 0.f);
        for (int i = 0; i < 64; ++i) {
            float4 v = *(const float4*)(base + (size_t)i * 1024);
            acc.x += v.x; acc.y += v.y; acc.z += v.z; acc.w += v.w;
        }
        *(float4*)(g_Ppart + b * 1024 + t * 4) = acc;
    } else if (b < 144) {
        int gid = (b - 128) * 256 + t;           // 0..4095
        if (gid < 1250) {                         // conv2 masks
            int oc = gid / 25, d = gid % 25;
            int dy = d / 5, dx = d % 5;
            unsigned mp = 0, mz = 0;
            for (int c = 0; c < 20; ++c) {
                float w = w2[oc * 500 + c * 25 + d];
                if (w > 0.f) mp |= 1u << c;
                else if (w == 0.f) mz |= 1u << c;
            }
            g_wp2[gid] = mp; g_wz2[gid] = mz;
            g_wp2p[(oc * 5 + dy) * 8 + dx] = mp;
            if (dx == 0) {                        // zero the pad words
                g_wp2p[(oc * 5 + dy) * 8 + 5] = 0;
                g_wp2p[(oc * 5 + dy) * 8 + 6] = 0;
                g_wp2p[(oc * 5 + dy) * 8 + 7] = 0;
            }
            if (mz) atomicOr(&g_zflag2, 1);
        }
        for (int e = gid; e < 500 * 40; e += 4096) {  // linear masks
            int j = e / 40, wi = e % 40;
            unsigned mp = 0, mz = 0;
            for (int bit = 0; bit < 32; ++bit) {
                int i = wi * 32 + bit;
                if (i < 1250) {
                    float w = wl[j * 1250 + i];
                    if (w > 0.f) mp |= 1u << bit;
                    else if (w == 0.f) mz |= 1u << bit;
                }
            }
            g_wpl[e] = mp; g_wzl[e] = mz;
            if (mz) atomicOr(&g_zflagl, 1);
        }
    } else {
        int w = (b - 144) * 8 + (t >> 5);        // row index
        int lane = t & 31;
        if (w < 500) {
            double s = 0.0;
            for (int i = lane; i < 1250; i += 32)
                s += fabs((double)wl[w * 1250 + i]);
#pragma unroll
            for (int o = 16; o; o >>= 1) s += __shfl_down_sync(0xffffffffu, s, o);
            if (lane == 0) g_alphal[w] = (float)(s / 1250.0);
        }
    }
}

// ---------------- K1b: reduce partials -> P, T[5][5], thresholds ----------
__global__ __launch_bounds__(1024) void k_thr(const float* __restrict__ w1) {
    __shared__ double Ps[1024];
    __shared__ double Ts[25];
    int t = threadIdx.x;
    double s0 = 0.0, s1 = 0.0;
    for (int i = 0; i < 128; i += 2) {
        s0 += (double)g_Ppart[i * 1024 + t];
        s1 += (double)g_Ppart[(i + 1) * 1024 + t];
    }
    Ps[t] = s0 + s1;
    __syncthreads();
    if (t < 800) {                    // 25 taps x 32 lanes, fixed shfl tree
        int g = t >> 5, lane = t & 31;
        int dy = g / 5, dx = g % 5;
        double a = 0.0;
        for (int idx = lane; idx < 784; idx += 32) {
            int i = idx / 28, j = idx % 28;
            a += Ps[(i + dy) * 32 + (j + dx)];
        }
#pragma unroll
        for (int o = 16; o; o >>= 1) a += __shfl_down_sync(0xffffffffu, a, o);
        if (lane == 0) Ts[g] = a;
    }
    __syncthreads();
    if (t < 20) {
        double d = 0.0;
        for (int k = 0; k < 25; ++k) d += (double)w1[t * 25 + k] * Ts[k];
        g_thr[t] = (float)(d / (8192.0 * 28.0 * 28.0));
    }
}

// ---------------- K2: conv1 + threshold + 2x2 pool + channel bit-pack -----
__global__ __launch_bounds__(224) void k_conv1(const float* __restrict__ x,
                                               const float* __restrict__ w1) {
    __shared__ float xs[1024];
    __shared__ float ws[20 * 28];
    __shared__ float thr_s[20];
    int n = blockIdx.x, t = threadIdx.x;
    for (int i = t; i < 1024; i += 224) xs[i] = x[(size_t)n * 1024 + i];
    for (int i = t; i < 500; i += 224) ws[(i / 25) * 28 + (i % 25)] = w1[i];
    if (t < 20) thr_s[t] = g_thr[t];
    __syncthreads();
    if (t < 196) {
        int py = t / 14, px = t % 14;
        float xp[6][6];
        const float* xb = &xs[(py * 2) * 32 + px * 2];
#pragma unroll
        for (int r = 0; r < 6; ++r) {
#pragma unroll
            for (int c2 = 0; c2 < 3; ++c2) {
                float2 v = *(const float2*)(xb + r * 32 + c2 * 2);
                xp[r][c2 * 2] = v.x; xp[r][c2 * 2 + 1] = v.y;
            }
        }
        unsigned word = 0;
#pragma unroll 1
        for (int c = 0; c < 20; ++c) {
            const float* wc = &ws[c * 28];
            float a0 = 0.f, a1 = 0.f, a2 = 0.f, a3 = 0.f;
#pragma unroll
            for (int dy = 0; dy < 5; ++dy) {
#pragma unroll
                for (int dx = 0; dx < 5; ++dx) {
                    float w = wc[dy * 5 + dx];
                    a0 = fmaf(w, xp[dy][dx],         a0);
                    a1 = fmaf(w, xp[dy][dx + 1],     a1);
                    a2 = fmaf(w, xp[dy + 1][dx],     a2);
                    a3 = fmaf(w, xp[dy + 1][dx + 1], a3);
                }
            }
            float m = fmaxf(fmaxf(a0, a1), fmaxf(a2, a3));
            if (m > thr_s[c]) word |= (1u << c);
        }
        g_b1[n * 196 + t] = word;
    }
}

// ---------------- K3: XNOR conv2 — LDS.128 b-rows, streamed W rows --------
#define C2_IMGS 2
#define ROWW 20                       // padded row width (words): 16B-aligned + bank-spread
__global__ __launch_bounds__(320) void k_conv2() {
    __shared__ __align__(16) unsigned BsA[C2_IMGS * 14 * ROWW];  // pixels 0..13
    __shared__ __align__(16) unsigned BsB[C2_IMGS * 14 * ROWW];  // pixels 2..13 (shifted by 2)
    __shared__ int PB[C2_IMGS][100];
    __shared__ __align__(16) unsigned Wps[50 * 5 * 8];           // padded W rows
    int n0 = blockIdx.x * C2_IMGS, t = threadIdx.x;
    for (int i = t; i < C2_IMGS * 196; i += 320) {
        int img = i / 196, p = i % 196;
        int y = p / 14, xx = p % 14;
        unsigned bv = g_b1[(size_t)(n0 + img) * 196 + p];
        BsA[img * 14 * ROWW + y * ROWW + xx] = bv;
        if (xx >= 2) BsB[img * 14 * ROWW + y * ROWW + xx - 2] = bv;
    }
    for (int i = t; i < 50 * 5 * 8; i += 320) Wps[i] = g_wp2p[i];
    __syncthreads();
    for (int i = t; i < C2_IMGS * 100; i += 320) {
        int img = i / 100, p = i % 100;
        int y = p / 10, xx = p % 10;
        const unsigned* B = &BsA[img * 14 * ROWW];
        int s = 0;
#pragma unroll
        for (int dy = 0; dy < 5; ++dy)
#pragma unroll
            for (int dx = 0; dx < 5; ++dx)
                s += __popc(B[(y + dy) * ROWW + xx + dx]);
        PB[img][p] = s;
    }
    __syncthreads();
    int zf = g_zflag2;
    int lane = t & 31, w = t >> 5;
#pragma unroll 1
    for (int k = 0; k < 4; ++k) {
        int f = k * 320 + t;
        int valid = f < 1250;
        int fc = valid ? f : 0;
        int oc = fc / 25; int rem = fc - oc * 25; int r = rem / 5; int cx = rem - r * 5;
        // patch base: even word offset; odd cx reads the shifted copy so the
        // uint4 stays 16B-aligned
        int odd = cx & 1;
        const unsigned* P0 = odd ? BsB : BsA;
        int rowbase = (2 * r) * ROWW + (odd ? (2 * cx - 2) : (2 * cx));
        const unsigned* Wbase = &Wps[oc * 5 * 8];
        int a00[C2_IMGS], a01[C2_IMGS], a10[C2_IMGS], a11[C2_IMGS];
#pragma unroll
        for (int img = 0; img < C2_IMGS; ++img) { a00[img] = 0; a01[img] = 0; a10[img] = 0; a11[img] = 0; }
        // streamed W rows: row rr feeds oy=0 at step rr and oy=1 at step rr+1
        unsigned pw0 = 0, pw1 = 0, pw2 = 0, pw3 = 0, pw4 = 0;
#pragma unroll
        for (int rr = 0; rr < 6; ++rr) {
            unsigned w0 = 0, w1 = 0, w2 = 0, w3 = 0, w4 = 0;
            if (rr < 5) {
                uint4 wq = *(const uint4*)(Wbase + rr * 8);
                w0 = wq.x; w1 = wq.y; w2 = wq.z; w3 = wq.w;
                w4 = Wbase[rr * 8 + 4];
            }
#pragma unroll
            for (int img = 0; img < C2_IMGS; ++img) {
                const unsigned* bp = P0 + img * 14 * ROWW + rowbase + rr * ROWW;
                uint4 q = *(const uint4*)bp;
                uint2 d2 = *(const uint2*)(bp + 4);
                unsigned p0 = q.x, p1 = q.y, p2 = q.z, p3 = q.w, p4 = d2.x, p5 = d2.y;
                if (rr < 5) {          // pool row oy=0 uses W row rr
                    a00[img] += __popc(p0 & w0) + __popc(p1 & w1) + __popc(p2 & w2)
                              + __popc(p3 & w3) + __popc(p4 & w4);
                    a01[img] += __popc(p1 & w0) + __popc(p2 & w1) + __popc(p3 & w2)
                              + __popc(p4 & w3) + __popc(p5 & w4);
                }
                if (rr >= 1) {         // pool row oy=1 uses W row rr-1 (prev)
                    a10[img] += __popc(p0 & pw0) + __popc(p1 & pw1) + __popc(p2 & pw2)
                              + __popc(p3 & pw3) + __popc(p4 & pw4);
                    a11[img] += __popc(p1 & pw0) + __popc(p2 & pw1) + __popc(p3 & pw2)
                              + __popc(p4 & pw3) + __popc(p5 & pw4);
                }
            }
            pw0 = w0; pw1 = w1; pw2 = w2; pw3 = w3; pw4 = w4;
        }
#pragma unroll
        for (int img = 0; img < C2_IMGS; ++img) {
            int bitP = 0, bitN = 0;
            if (valid) {
                int v00 = 2 * a00[img] - PB[img][(2 * r) * 10 + 2 * cx];
                int v01 = 2 * a01[img] - PB[img][(2 * r) * 10 + 2 * cx + 1];
                int v10 = 2 * a10[img] - PB[img][(2 * r + 1) * 10 + 2 * cx];
                int v11 = 2 * a11[img] - PB[img][(2 * r + 1) * 10 + 2 * cx + 1];
                if (zf) {  // uniform, never taken with this dataset
                    const unsigned* B = &BsA[img * 14 * ROWW + (2 * r) * ROWW + 2 * cx];
                    int z00 = 0, z01 = 0, z10 = 0, z11 = 0;
                    for (int dy = 0; dy < 5; ++dy)
                        for (int dx = 0; dx < 5; ++dx) {
                            unsigned wz = g_wz2[oc * 25 + dy * 5 + dx];
                            z00 += __popc(B[dy * ROWW + dx] & wz);
                            z01 += __popc(B[dy * ROWW + dx + 1] & wz);
                            z10 += __popc(B[(dy + 1) * ROWW + dx] & wz);
                            z11 += __popc(B[(dy + 1) * ROWW + dx + 1] & wz);
                        }
                    v00 += z00; v01 += z01; v10 += z10; v11 += z11;
                }
                int best = max(max(v00, v01), max(v10, v11));
                bitP = best > 0; bitN = best < 0;
            }
            unsigned mp = __ballot_sync(0xffffffffu, bitP);
            unsigned mn = __ballot_sync(0xffffffffu, bitN);
            if (lane == 0) {
                int wi = k * 10 + w;
                g_Bp[(size_t)(n0 + img) * 40 + wi] = mp;
                g_Bn[(size_t)(n0 + img) * 40 + wi] = mn;
            }
        }
    }
}

// ---------------- K4: binary linear (XNOR-LOP3) + clip + fc ---------------
__global__ __launch_bounds__(256) void k_dense(const float* __restrict__ fcw,
                                               const float* __restrict__ fcb,
                                               float* __restrict__ out) {
    extern __shared__ unsigned sm[];
    unsigned* Ws  = sm;                       // 500*41 (padded, conflict-free)
    unsigned* Bps = Ws + 500 * 41;            // 8*40  sign bit-plane (+1)
    unsigned* Bns = Bps + 8 * 40;             // 8*40  sign bit-plane (-1), zf path only
    unsigned* Us  = Bns + 8 * 40;             // 8*40  nonzero mask = Bp|Bn
    int*      pcU = (int*)(Us + 8 * 40);      // 8
    float*    hs  = (float*)(pcU + 8);        // 8*500
    int t = threadIdx.x;
    int n0 = blockIdx.x * 8;
    for (int i = t; i < 500 * 40; i += 256) Ws[(i / 40) * 41 + (i % 40)] = g_wpl[i];
    for (int i = t; i < 320; i += 256) {
        int img = i / 40, wi = i % 40;
        unsigned bp = g_Bp[(size_t)(n0 + img) * 40 + wi];
        unsigned bn = g_Bn[(size_t)(n0 + img) * 40 + wi];
        Bps[img * 40 + wi] = bp;
        Bns[img * 40 + wi] = bn;
        Us[img * 40 + wi]  = bp | bn;
    }
    __syncthreads();
    if (t < 8) {
        int s = 0;
        for (int k = 0; k < 40; ++k) s += __popc(Us[t * 40 + k]);
        pcU[t] = s;
    }
    __syncthreads();
    int zf = g_zflagl;
    for (int j = t; j < 500; j += 256) {
        unsigned wr[40];
#pragma unroll
        for (int k = 0; k < 40; ++k) wr[k] = Ws[j * 41 + k];
        float al = g_alphal[j];
#pragma unroll 1
        for (int img = 0; img < 8; ++img) {
            int m = 0;
#pragma unroll
            for (int k = 0; k < 40; ++k) {
                // agreement over nonzero lanes: one LOP3 per word
                m += __popc((~(Bps[img * 40 + k] ^ wr[k])) & Us[img * 40 + k]);
            }
            int vi = 2 * m - pcU[img];
            if (zf) {  // uniform, never taken with this dataset
                int cp = 0, cn = 0;
                for (int k = 0; k < 40; ++k) {
                    unsigned z = g_wzl[j * 40 + k];
                    cp += __popc(Bps[img * 40 + k] & z);
                    cn += __popc(Bns[img * 40 + k] & z);
                }
                vi += cp - cn;
            }
            float h = fminf(fmaxf((float)vi * al, -1.f), 1.f);
            hs[img * 500 + j] = h;
        }
    }
    __syncthreads();
    int w = t >> 5, lane = t & 31;   // warp w -> image w
    for (int lg = 0; lg < 10; ++lg) {
        float p = 0.f;
        for (int j = lane; j < 500; j += 32)
            p += hs[w * 500 + j] * __ldg(&fcw[lg * 500 + j]);
#pragma unroll
        for (int o = 16; o; o >>= 1) p += __shfl_down_sync(0xffffffffu, p, o);
        if (lane == 0) out[(size_t)(n0 + w) * 10 + lg] = p + fcb[lg];
    }
}

// ---------------- launch ---------------------------------------------------
extern "C" void kernel_launch(void* const* d_in, const int* in_sizes, int n_in,
                              void* d_out, int out_size) {
    const float* x   = (const float*)d_in[0];
    const float* w1  = (const float*)d_in[1];
    const float* w2  = (const float*)d_in[2];
    const float* wl  = (const float*)d_in[3];
    const float* fcw = (const float*)d_in[4];
    const float* fcb = (const float*)d_in[5];
    float* out = (float*)d_out;

    size_t dense_smem = (500 * 41 + 8 * 40 * 3 + 8) * 4 + 8 * 500 * 4;
    cudaFuncSetAttribute(k_dense, cudaFuncAttributeMaxDynamicSharedMemorySize,
                         (int)dense_smem);

    k_pre<<<207, 256>>>(x, w2, wl);
    k_thr<<<1, 1024>>>(w1);
    k_conv1<<<8192, 224>>>(x, w1);
    k_conv2<<<N_IMG / C2_IMGS, 320>>>();
    k_dense<<<1024, 256, dense_smem>>>(fcw, fcb, out);
}

// round 8
// speedup vs baseline: 1.0433x; 1.0183x over previous
#include <cuda_runtime.h>
#include <cstdint>

#define N_IMG 8192

// ---------------- scratch (device globals; no allocations) ----------------
__device__ float    g_Ppart[128 * 1024];     // partial batch sums of x
__device__ float    g_thr[20];               // per-channel BN mean (threshold)
__device__ unsigned g_b1[N_IMG * 196];       // binarized pool1: 20 channel bits per (n,py,px)
__device__ unsigned g_wp2[50 * 25];          // conv2 sign(W)>0 masks (20 bits over c)
__device__ unsigned g_wp2p[50 * 5 * 8];      // conv2 masks, 8-word padded rows (w0..w4,0,0,0)
__device__ unsigned g_wz2[50 * 25];          // conv2 W==0 masks
__device__ int      g_zflag2;                // any zero conv2 weight
__device__ unsigned g_wpl[500 * 40];         // linear sign(W)>0 masks (1250 bits)
__device__ unsigned g_wzl[500 * 40];         // linear W==0 masks
__device__ int      g_zflagl;
__device__ float    g_alphal[500];           // linear alpha = mean(|W|, dim=1)
__device__ unsigned g_Bp[N_IMG * 40];        // sign(+1) bit-plane into linear
__device__ unsigned g_Bn[N_IMG * 40];        // sign(-1) bit-plane into linear

// ---------------- K_pre: fused colsum + weight masks + alpha_l ------------
__global__ __launch_bounds__(256) void k_pre(const float* __restrict__ x,
                                             const float* __restrict__ w2,
                                             const float* __restrict__ wl) {
    int b = blockIdx.x, t = threadIdx.x;
    if (b < 128) {
        const float* base = x + (size_t)b * 64 * 1024 + t * 4;
        float4 acc = make_float4(0.f, 0.f, 0.f, 0.f);
        for (int i = 0; i < 64; ++i) {
            float4 v = *(const float4*)(base + (size_t)i * 1024);
            acc.x += v.x; acc.y += v.y; acc.z += v.z; acc.w += v.w;
        }
        *(float4*)(g_Ppart + b * 1024 + t * 4) = acc;
    } else if (b < 144) {
        int gid = (b - 128) * 256 + t;           // 0..4095
        if (gid < 1250) {                         // conv2 masks
            int oc = gid / 25, d = gid % 25;
            int dy = d / 5, dx = d % 5;
            unsigned mp = 0, mz = 0;
            for (int c = 0; c < 20; ++c) {
                float w = w2[oc * 500 + c * 25 + d];
                if (w > 0.f) mp |= 1u << c;
                else if (w == 0.f) mz |= 1u << c;
            }
            g_wp2[gid] = mp; g_wz2[gid] = mz;
            g_wp2p[(oc * 5 + dy) * 8 + dx] = mp;
            if (dx == 0) {                        // zero the pad words
                g_wp2p[(oc * 5 + dy) * 8 + 5] = 0;
                g_wp2p[(oc * 5 + dy) * 8 + 6] = 0;
                g_wp2p[(oc * 5 + dy) * 8 + 7] = 0;
            }
            if (mz) atomicOr(&g_zflag2, 1);
        }
        for (int e = gid; e < 500 * 40; e += 4096) {  // linear masks
            int j = e / 40, wi = e % 40;
            unsigned mp = 0, mz = 0;
            for (int bit = 0; bit < 32; ++bit) {
                int i = wi * 32 + bit;
                if (i < 1250) {
                    float w = wl[j * 1250 + i];
                    if (w > 0.f) mp |= 1u << bit;
                    else if (w == 0.f) mz |= 1u << bit;
                }
            }
            g_wpl[e] = mp; g_wzl[e] = mz;
            if (mz) atomicOr(&g_zflagl, 1);
        }
    } else {
        int w = (b - 144) * 8 + (t >> 5);        // row index
        int lane = t & 31;
        if (w < 500) {
            double s = 0.0;
            for (int i = lane; i < 1250; i += 32)
                s += fabs((double)wl[w * 1250 + i]);
#pragma unroll
            for (int o = 16; o; o >>= 1) s += __shfl_down_sync(0xffffffffu, s, o);
            if (lane == 0) g_alphal[w] = (float)(s / 1250.0);
        }
    }
}

// ---------------- K1b: reduce partials -> P, T[5][5], thresholds ----------
__global__ __launch_bounds__(1024) void k_thr(const float* __restrict__ w1) {
    __shared__ double Ps[1024];
    __shared__ double Ts[25];
    int t = threadIdx.x;
    double s0 = 0.0, s1 = 0.0;
    for (int i = 0; i < 128; i += 2) {
        s0 += (double)g_Ppart[i * 1024 + t];
        s1 += (double)g_Ppart[(i + 1) * 1024 + t];
    }
    Ps[t] = s0 + s1;
    __syncthreads();
    if (t < 800) {                    // 25 taps x 32 lanes, fixed shfl tree
        int g = t >> 5, lane = t & 31;
        int dy = g / 5, dx = g % 5;
        double a = 0.0;
        for (int idx = lane; idx < 784; idx += 32) {
            int i = idx / 28, j = idx % 28;
            a += Ps[(i + dy) * 32 + (j + dx)];
        }
#pragma unroll
        for (int o = 16; o; o >>= 1) a += __shfl_down_sync(0xffffffffu, a, o);
        if (lane == 0) Ts[g] = a;
    }
    __syncthreads();
    if (t < 20) {
        double d = 0.0;
        for (int k = 0; k < 25; ++k) d += (double)w1[t * 25 + k] * Ts[k];
        g_thr[t] = (float)(d / (8192.0 * 28.0 * 28.0));
    }
}

// ---------------- K2: conv1 + threshold + 2x2 pool + channel bit-pack -----
__global__ __launch_bounds__(224) void k_conv1(const float* __restrict__ x,
                                               const float* __restrict__ w1) {
    __shared__ float xs[1024];
    __shared__ float ws[20 * 28];
    __shared__ float thr_s[20];
    int n = blockIdx.x, t = threadIdx.x;
    for (int i = t; i < 1024; i += 224) xs[i] = x[(size_t)n * 1024 + i];
    for (int i = t; i < 500; i += 224) ws[(i / 25) * 28 + (i % 25)] = w1[i];
    if (t < 20) thr_s[t] = g_thr[t];
    __syncthreads();
    if (t < 196) {
        int py = t / 14, px = t % 14;
        float xp[6][6];
        const float* xb = &xs[(py * 2) * 32 + px * 2];
#pragma unroll
        for (int r = 0; r < 6; ++r) {
#pragma unroll
            for (int c2 = 0; c2 < 3; ++c2) {
                float2 v = *(const float2*)(xb + r * 32 + c2 * 2);
                xp[r][c2 * 2] = v.x; xp[r][c2 * 2 + 1] = v.y;
            }
        }
        unsigned word = 0;
#pragma unroll 1
        for (int c = 0; c < 20; ++c) {
            const float* wc = &ws[c * 28];
            float a0 = 0.f, a1 = 0.f, a2 = 0.f, a3 = 0.f;
#pragma unroll
            for (int dy = 0; dy < 5; ++dy) {
#pragma unroll
                for (int dx = 0; dx < 5; ++dx) {
                    float w = wc[dy * 5 + dx];
                    a0 = fmaf(w, xp[dy][dx],         a0);
                    a1 = fmaf(w, xp[dy][dx + 1],     a1);
                    a2 = fmaf(w, xp[dy + 1][dx],     a2);
                    a3 = fmaf(w, xp[dy + 1][dx + 1], a3);
                }
            }
            float m = fmaxf(fmaxf(a0, a1), fmaxf(a2, a3));
            if (m > thr_s[c]) word |= (1u << c);
        }
        g_b1[n * 196 + t] = word;
    }
}

// ---------------- K3: XNOR conv2 — thread per (oc,cx), W in regs ----------
#define C2_IMGS 2
#define ROWW 20                       // padded row width (words)
__global__ __launch_bounds__(256) void k_conv2() {
    __shared__ __align__(16) unsigned BsA[C2_IMGS * 14 * ROWW];  // pixels 0..13
    __shared__ __align__(16) unsigned BsB[C2_IMGS * 14 * ROWW];  // pixels shifted by 2
    __shared__ int PB[C2_IMGS][100];
    __shared__ __align__(16) unsigned Wps[50 * 5 * 8];           // padded W rows
    __shared__ __align__(16) unsigned char sPN[C2_IMGS][1280];   // bit0=P, bit1=N per output
    int n0 = blockIdx.x * C2_IMGS, t = threadIdx.x;
    for (int i = t; i < C2_IMGS * 196; i += 256) {
        int img = i / 196, p = i % 196;
        int y = p / 14, xx = p % 14;
        unsigned bv = g_b1[(size_t)(n0 + img) * 196 + p];
        BsA[img * 14 * ROWW + y * ROWW + xx] = bv;
        if (xx >= 2) BsB[img * 14 * ROWW + y * ROWW + xx - 2] = bv;
    }
    for (int i = t; i < 50 * 5 * 8; i += 256) Wps[i] = g_wp2p[i];
    if (t < C2_IMGS * 30) {                    // zero pad bytes [1250,1280)
        sPN[t / 30][1250 + (t % 30)] = 0;
    }
    __syncthreads();
    for (int i = t; i < C2_IMGS * 100; i += 256) {
        int img = i / 100, p = i % 100;
        int y = p / 10, xx = p % 10;
        const unsigned* B = &BsA[img * 14 * ROWW];
        int s = 0;
#pragma unroll
        for (int dy = 0; dy < 5; ++dy)
#pragma unroll
            for (int dx = 0; dx < 5; ++dx)
                s += __popc(B[(y + dy) * ROWW + xx + dx]);
        PB[img][p] = s;
    }
    __syncthreads();
    int zf = g_zflag2;
    if (t < 250) {
        int oc = t / 5, cx = t % 5;
        int odd = cx & 1;
        const unsigned* P0 = odd ? BsB : BsA;
        int colbase = odd ? (2 * cx - 2) : (2 * cx);
        unsigned W[25];
#pragma unroll
        for (int j = 0; j < 5; ++j) {
            uint4 wq = *(const uint4*)(&Wps[oc * 40 + j * 8]);
            W[j * 5] = wq.x; W[j * 5 + 1] = wq.y; W[j * 5 + 2] = wq.z; W[j * 5 + 3] = wq.w;
            W[j * 5 + 4] = Wps[oc * 40 + j * 8 + 4];
        }
#pragma unroll 1
        for (int r = 0; r < 5; ++r) {
#pragma unroll 1
            for (int img = 0; img < C2_IMGS; ++img) {
                const unsigned* bp0 = P0 + img * 14 * ROWW + (2 * r) * ROWW + colbase;
                int a00 = 0, a01 = 0, a10 = 0, a11 = 0;
#pragma unroll
                for (int rr = 0; rr < 6; ++rr) {
                    const unsigned* bp = bp0 + rr * ROWW;
                    uint4 q = *(const uint4*)bp;
                    uint2 d2 = *(const uint2*)(bp + 4);
                    unsigned p0 = q.x, p1 = q.y, p2 = q.z, p3 = q.w, p4 = d2.x, p5 = d2.y;
                    if (rr < 5) {          // pool row oy=0 uses W row rr
                        a00 += __popc(p0 & W[rr * 5]) + __popc(p1 & W[rr * 5 + 1])
                             + __popc(p2 & W[rr * 5 + 2]) + __popc(p3 & W[rr * 5 + 3])
                             + __popc(p4 & W[rr * 5 + 4]);
                        a01 += __popc(p1 & W[rr * 5]) + __popc(p2 & W[rr * 5 + 1])
                             + __popc(p3 & W[rr * 5 + 2]) + __popc(p4 & W[rr * 5 + 3])
                             + __popc(p5 & W[rr * 5 + 4]);
                    }
                    if (rr >= 1) {         // pool row oy=1 uses W row rr-1
                        a10 += __popc(p0 & W[(rr - 1) * 5]) + __popc(p1 & W[(rr - 1) * 5 + 1])
                             + __popc(p2 & W[(rr - 1) * 5 + 2]) + __popc(p3 & W[(rr - 1) * 5 + 3])
                             + __popc(p4 & W[(rr - 1) * 5 + 4]);
                        a11 += __popc(p1 & W[(rr - 1) * 5]) + __popc(p2 & W[(rr - 1) * 5 + 1])
                             + __popc(p3 & W[(rr - 1) * 5 + 2]) + __popc(p4 & W[(rr - 1) * 5 + 3])
                             + __popc(p5 & W[(rr - 1) * 5 + 4]);
                    }
                }
                int v00 = 2 * a00 - PB[img][(2 * r) * 10 + 2 * cx];
                int v01 = 2 * a01 - PB[img][(2 * r) * 10 + 2 * cx + 1];
                int v10 = 2 * a10 - PB[img][(2 * r + 1) * 10 + 2 * cx];
                int v11 = 2 * a11 - PB[img][(2 * r + 1) * 10 + 2 * cx + 1];
                if (zf) {  // uniform, never taken with this dataset
                    const unsigned* B = &BsA[img * 14 * ROWW + (2 * r) * ROWW + 2 * cx];
                    int z00 = 0, z01 = 0, z10 = 0, z11 = 0;
                    for (int dy = 0; dy < 5; ++dy)
                        for (int dx = 0; dx < 5; ++dx) {
                            unsigned wz = g_wz2[oc * 25 + dy * 5 + dx];
                            z00 += __popc(B[dy * ROWW + dx] & wz);
                            z01 += __popc(B[dy * ROWW + dx + 1] & wz);
                            z10 += __popc(B[(dy + 1) * ROWW + dx] & wz);
                            z11 += __popc(B[(dy + 1) * ROWW + dx + 1] & wz);
                        }
                    v00 += z00; v01 += z01; v10 += z10; v11 += z11;
                }
                int best = max(max(v00, v01), max(v10, v11));
                sPN[img][oc * 25 + r * 5 + cx] =
                    (unsigned char)((best > 0 ? 1 : 0) | (best < 0 ? 2 : 0));
            }
        }
    }
    __syncthreads();
    if (t < C2_IMGS * 40) {                    // byte planes -> bit planes
        int img = t / 40, wi = t % 40;
        const unsigned* src = (const unsigned*)&sPN[img][0] + wi * 8;
        unsigned P = 0, N = 0;
#pragma unroll
        for (int j = 0; j < 8; ++j) {
            unsigned b = src[j];
            P |= ((((b & 0x01010101u) * 0x00204081u) >> 21) & 0xFu) << (4 * j);
            N |= (((((b >> 1) & 0x01010101u) * 0x00204081u) >> 21) & 0xFu) << (4 * j);
        }
        g_Bp[(size_t)(n0 + img) * 40 + wi] = P;
        g_Bn[(size_t)(n0 + img) * 40 + wi] = N;
    }
}

// ---------------- K4: binary linear (XNOR-LOP3) + clip + fc, 16 imgs ------
#define D_IMGS 16
__global__ __launch_bounds__(512) void k_dense(const float* __restrict__ fcw,
                                               const float* __restrict__ fcb,
                                               float* __restrict__ out) {
    extern __shared__ unsigned sm[];
    unsigned* Ws  = sm;                       // 500*41 (padded, conflict-free)
    unsigned* Bps = Ws + 500 * 41;            // D*40  sign bit-plane (+1)
    unsigned* Bns = Bps + D_IMGS * 40;        // D*40  sign bit-plane (-1), zf path only
    unsigned* Us  = Bns + D_IMGS * 40;        // D*40  nonzero mask = Bp|Bn
    int*      pcU = (int*)(Us + D_IMGS * 40); // D
    float*    hs  = (float*)(pcU + D_IMGS);   // D*500
    int t = threadIdx.x;
    int n0 = blockIdx.x * D_IMGS;
    for (int i = t; i < 500 * 40; i += 512) Ws[(i / 40) * 41 + (i % 40)] = g_wpl[i];
    for (int i = t; i < D_IMGS * 40; i += 512) {
        int img = i / 40, wi = i % 40;
        unsigned bp = g_Bp[(size_t)(n0 + img) * 40 + wi];
        unsigned bn = g_Bn[(size_t)(n0 + img) * 40 + wi];
        Bps[img * 40 + wi] = bp;
        Bns[img * 40 + wi] = bn;
        Us[img * 40 + wi]  = bp | bn;
    }
    __syncthreads();
    if (t < D_IMGS) {
        int s = 0;
        for (int k = 0; k < 40; ++k) s += __popc(Us[t * 40 + k]);
        pcU[t] = s;
    }
    __syncthreads();
    int zf = g_zflagl;
    for (int j = t; j < 500; j += 512) {
        unsigned wr[40];
#pragma unroll
        for (int k = 0; k < 40; ++k) wr[k] = Ws[j * 41 + k];
        float al = g_alphal[j];
#pragma unroll 1
        for (int img = 0; img < D_IMGS; ++img) {
            int m = 0;
#pragma unroll
            for (int k = 0; k < 40; ++k) {
                // agreement over nonzero lanes: one LOP3 per word
                m += __popc((~(Bps[img * 40 + k] ^ wr[k])) & Us[img * 40 + k]);
            }
            int vi = 2 * m - pcU[img];
            if (zf) {  // uniform, never taken with this dataset
                int cp = 0, cn = 0;
                for (int k = 0; k < 40; ++k) {
                    unsigned z = g_wzl[j * 40 + k];
                    cp += __popc(Bps[img * 40 + k] & z);
                    cn += __popc(Bns[img * 40 + k] & z);
                }
                vi += cp - cn;
            }
            float h = fminf(fmaxf((float)vi * al, -1.f), 1.f);
            hs[img * 500 + j] = h;
        }
    }
    __syncthreads();
    int w = t >> 5, lane = t & 31;   // warp w -> image w
    for (int lg = 0; lg < 10; ++lg) {
        float p = 0.f;
        for (int j = lane; j < 500; j += 32)
            p += hs[w * 500 + j] * __ldg(&fcw[lg * 500 + j]);
#pragma unroll
        for (int o = 16; o; o >>= 1) p += __shfl_down_sync(0xffffffffu, p, o);
        if (lane == 0) out[(size_t)(n0 + w) * 10 + lg] = p + fcb[lg];
    }
}

// ---------------- launch ---------------------------------------------------
extern "C" void kernel_launch(void* const* d_in, const int* in_sizes, int n_in,
                              void* d_out, int out_size) {
    const float* x   = (const float*)d_in[0];
    const float* w1  = (const float*)d_in[1];
    const float* w2  = (const float*)d_in[2];
    const float* wl  = (const float*)d_in[3];
    const float* fcw = (const float*)d_in[4];
    const float* fcb = (const float*)d_in[5];
    float* out = (float*)d_out;

    size_t dense_smem = (500 * 41 + D_IMGS * 40 * 3 + D_IMGS) * 4 + D_IMGS * 500 * 4;
    cudaFuncSetAttribute(k_dense, cudaFuncAttributeMaxDynamicSharedMemorySize,
                         (int)dense_smem);

    k_pre<<<207, 256>>>(x, w2, wl);
    k_thr<<<1, 1024>>>(w1);
    k_conv1<<<8192, 224>>>(x, w1);
    k_conv2<<<N_IMG / C2_IMGS, 256>>>();
    k_dense<<<N_IMG / D_IMGS, 512, dense_smem>>>(fcw, fcb, out);
}